// round 12
// baseline (speedup 1.0000x reference)
#include <cuda_runtime.h>
#include <math.h>
#include <stdint.h>

// ---------------------------------------------------------------------------
// DecoderBlock (DiT-style): AdaLN -> MHA -> residual -> AdaLN -> FFN -> residual
// B=2, S=2048 (T=4096 tokens), D=1024, H=16, d=64, D_COND=512, FF=4096, fp32.
// tf32 HMMA (tcgen05 unavailable on this toolchain: targets sm_103 w/o 'a').
// Weights pre-rounded tf32 + pre-transposed [N][K]; ldmatrix.x4 fragments;
// BK=16, 4-stage cp.async ring, 2 CTA/SM. Fused gb GEMM; split-K x2 for f2;
// single prologue mega-kernel (cvt+silu+bias).
// ---------------------------------------------------------------------------

#define T_TOK 4096

__device__ float g_sc  [T_TOK * 512];
__device__ float g_gb12[T_TOK * 4096];   // fused [gamma1|beta1|gamma2|beta2]
__device__ float g_h   [T_TOK * 1024];
__device__ float g_qkv [T_TOK * 3072];
__device__ float g_attn[T_TOK * 1024];
__device__ float g_x2  [T_TOK * 1024];
__device__ float g_h2  [T_TOK * 1024];
__device__ float g_ff  [T_TOK * 4096];
__device__ float g_pk  [2 * T_TOK * 1024];   // f2 split-K partials
// tf32-rounded, TRANSPOSED ([N][K]) weight copies
__device__ float g_wgb [4096 * 512];     // rows 0-2047: p1_w^T, rows 2048-4095: p2_w^T
__device__ float g_bgb [4096];           // p1_b | p2_b
__device__ float g_wqkv[3072 * 1024];
__device__ float g_wao [1024 * 1024];
__device__ float g_wf1 [4096 * 1024];
__device__ float g_wf2 [1024 * 4096];

enum { EPI_NONE = 0, EPI_BIAS = 1, EPI_BIAS_GELU = 2, EPI_RES = 3, EPI_BIAS_RES = 4 };

__device__ __forceinline__ float gelu_exact(float v) {
    return 0.5f * v * (1.0f + erff(v * 0.70710678118654752440f));
}

__device__ __forceinline__ float to_tf32(float x) {
    uint32_t u;
    asm("cvt.rna.tf32.f32 %0, %1;" : "=r"(u) : "f"(x));
    return __uint_as_float(u);
}

__device__ __forceinline__ void mma_tf32(float* c,
    uint32_t a0, uint32_t a1, uint32_t a2, uint32_t a3, uint32_t b0, uint32_t b1)
{
    asm volatile(
        "mma.sync.aligned.m16n8k8.row.col.f32.tf32.tf32.f32 "
        "{%0,%1,%2,%3},{%4,%5,%6,%7},{%8,%9},{%0,%1,%2,%3};\n"
        : "+f"(c[0]), "+f"(c[1]), "+f"(c[2]), "+f"(c[3])
        : "r"(a0), "r"(a1), "r"(a2), "r"(a3), "r"(b0), "r"(b1));
}

__device__ __forceinline__ void ldsm_x4(uint32_t* r, uint32_t saddr) {
    asm volatile("ldmatrix.sync.aligned.m8n8.x4.shared.b16 {%0,%1,%2,%3}, [%4];"
                 : "=r"(r[0]), "=r"(r[1]), "=r"(r[2]), "=r"(r[3]) : "r"(saddr));
}

__device__ __forceinline__ void cp16(float* smem_dst, const float* gsrc) {
    uint32_t d = (uint32_t)__cvta_generic_to_shared(smem_dst);
    asm volatile("cp.async.cg.shared.global [%0], [%1], 16;\n" :: "r"(d), "l"(gsrc));
}
__device__ __forceinline__ void cp_commit() {
    asm volatile("cp.async.commit_group;\n");
}
template <int N>
__device__ __forceinline__ void cp_wait() {
    asm volatile("cp.async.wait_group %0;\n" :: "n"(N));
}

// ---------------------------------------------------------------------------
// Prologue mega-kernel: weight cvt+transpose (14336 tiles) + silu (2048 blks)
// + bias concat (4 blks) in ONE launch.
// ---------------------------------------------------------------------------
__global__ __launch_bounds__(256) void prologue_all(
    const float* __restrict__ p1, const float* __restrict__ p2,
    const float* __restrict__ qk, const float* __restrict__ ao,
    const float* __restrict__ f1, const float* __restrict__ f2,
    const float4* __restrict__ cond,
    const float4* __restrict__ b1, const float4* __restrict__ b2,
    float* __restrict__ ogb, float* __restrict__ oq,
    float* __restrict__ oa, float* __restrict__ of1, float* __restrict__ of2,
    float4* __restrict__ sc, float4* __restrict__ bgb)
{
    __shared__ float t[32][33];
    int blk = blockIdx.x;
    int tid = threadIdx.x;
    if (blk < 14336) {
        const float* src; float* dst; int K, N, tile;
        if      (blk < 1024)  { src = p1; dst = ogb;              K = 512;  N = 2048; tile = blk; }
        else if (blk < 2048)  { src = p2; dst = ogb + 2048 * 512; K = 512;  N = 2048; tile = blk - 1024; }
        else if (blk < 5120)  { src = qk; dst = oq;               K = 1024; N = 3072; tile = blk - 2048; }
        else if (blk < 6144)  { src = ao; dst = oa;               K = 1024; N = 1024; tile = blk - 5120; }
        else if (blk < 10240) { src = f1; dst = of1;              K = 1024; N = 4096; tile = blk - 6144; }
        else                  { src = f2; dst = of2;              K = 4096; N = 1024; tile = blk - 10240; }
        const int ntx = N >> 5;
        const int n0 = (tile % ntx) * 32;
        const int k0 = (tile / ntx) * 32;
        const int tx = tid & 31;
        const int ty = tid >> 5;
        #pragma unroll
        for (int i = 0; i < 32; i += 8)
            t[ty + i][tx] = to_tf32(src[(size_t)(k0 + ty + i) * N + n0 + tx]);
        __syncthreads();
        #pragma unroll
        for (int i = 0; i < 32; i += 8)
            dst[(size_t)(n0 + ty + i) * K + k0 + tx] = t[tx][ty + i];
    } else if (blk < 16384) {
        // silu: 524288 float4 total, 256 per block
        int i = (blk - 14336) * 256 + tid;
        float4 v = cond[i];
        sc[i] = make_float4(
            to_tf32(v.x / (1.0f + __expf(-v.x))),
            to_tf32(v.y / (1.0f + __expf(-v.y))),
            to_tf32(v.z / (1.0f + __expf(-v.z))),
            to_tf32(v.w / (1.0f + __expf(-v.w))));
    } else {
        // bias concat: 1024 float4
        int i = (blk - 16384) * 256 + tid;
        bgb[i] = (i < 512) ? b1[i] : b2[i - 512];
    }
}

// ---------------------------------------------------------------------------
// tf32 GEMM: C(MxN) = A(MxK) @ Bt(NxK)^T [+bias][+gelu][+res]
// Block 128x128, BK=16, 256 threads (8 warps, 2x4), warp tile 64x32.
// A row-major [M][Kstride]; Bt row-major [N][Kstride] (tf32-prerounded).
// Split-K via blockIdx.z: z-th chunk of Klen columns, C += z*M*N.
// 4-stage cp.async ring, ldmatrix.x4 frags, 2 CTAs/SM.
// ---------------------------------------------------------------------------
#define GST (128 * 20)
#define GSS (2 * GST)
#define GEMM_STAGES 4
#define GEMM_SMEM_BYTES (GEMM_STAGES * GSS * 4)

template <int EPI>
__global__ __launch_bounds__(256, 2) void tf32gemm(
    const float* __restrict__ A, const float* __restrict__ Bt, float* __restrict__ C,
    int M, int N, int Kstride, int Klen,
    const float* __restrict__ bias, const float* __restrict__ res)
{
    extern __shared__ float sm[];

    const int tid  = threadIdx.x;
    const int bx   = blockIdx.x;
    const int by   = blockIdx.y;
    const int kz   = blockIdx.z;
    const int lane = tid & 31;
    const int wid  = tid >> 5;
    const int wm   = (wid >> 2) * 64;   // 0 or 64
    const int wn   = (wid & 3) * 32;    // 0,32,64,96
    const int gr   = lane >> 2;
    const int gc   = lane & 3;

    const int rowsel = (lane & 7) + ((lane >> 3) & 1) * 8;  // 0..15
    const int kadd   = (lane >> 4) * 4;                     // 0 or 4

    const int srow = tid >> 1;
    const int scol = (tid & 1) * 8;
    const size_t koff = (size_t)kz * Klen;
    const float* Agb = A  + (size_t)(by * 128 + srow) * Kstride + koff + scol;
    const float* Bgb = Bt + (size_t)(bx * 128 + srow) * Kstride + koff + scol;
    C += (size_t)kz * M * N;

    const int nk = Klen >> 4;

    float acc[4][4][4];
    #pragma unroll
    for (int mi = 0; mi < 4; mi++)
        #pragma unroll
        for (int ni = 0; ni < 4; ni++)
            #pragma unroll
            for (int q = 0; q < 4; q++) acc[mi][ni][q] = 0.0f;

    // prologue: stages 0..2
    #pragma unroll
    for (int s = 0; s < GEMM_STAGES - 1; s++) {
        float* as = sm + s * GSS;
        float* bs = as + GST;
        cp16(as + srow * 20 + scol,     Agb + s * 16);
        cp16(as + srow * 20 + scol + 4, Agb + s * 16 + 4);
        cp16(bs + srow * 20 + scol,     Bgb + s * 16);
        cp16(bs + srow * 20 + scol + 4, Bgb + s * 16 + 4);
        cp_commit();
    }

    const uint32_t smemBase = (uint32_t)__cvta_generic_to_shared(sm);

    for (int kt = 0; kt < nk; kt++) {
        cp_wait<GEMM_STAGES - 2>();
        __syncthreads();

        if (kt + GEMM_STAGES - 1 < nk) {
            int s = (kt + GEMM_STAGES - 1) % GEMM_STAGES;
            float* as = sm + s * GSS;
            float* bs = as + GST;
            cp16(as + srow * 20 + scol,     Agb + (kt + GEMM_STAGES - 1) * 16);
            cp16(as + srow * 20 + scol + 4, Agb + (kt + GEMM_STAGES - 1) * 16 + 4);
            cp16(bs + srow * 20 + scol,     Bgb + (size_t)(kt + GEMM_STAGES - 1) * 16);
            cp16(bs + srow * 20 + scol + 4, Bgb + (size_t)(kt + GEMM_STAGES - 1) * 16 + 4);
        }
        cp_commit();

        const uint32_t asAddr = smemBase + ((kt % GEMM_STAGES) * GSS) * 4;
        const uint32_t bsAddr = asAddr + GST * 4;
        const uint32_t aBase = asAddr + ((wm + rowsel) * 20 + kadd) * 4;
        const uint32_t bBase = bsAddr + ((wn + rowsel) * 20 + kadd) * 4;

        #pragma unroll
        for (int k8 = 0; k8 < 16; k8 += 8) {
            uint32_t af[4][4], bf[2][4];
            #pragma unroll
            for (int mi = 0; mi < 4; mi++)
                ldsm_x4(af[mi], aBase + (mi * 16 * 20 + k8) * 4);
            #pragma unroll
            for (int p = 0; p < 2; p++)
                ldsm_x4(bf[p], bBase + (p * 16 * 20 + k8) * 4);
            #pragma unroll
            for (int mi = 0; mi < 4; mi++)
                #pragma unroll
                for (int ni = 0; ni < 4; ni++)
                    mma_tf32(acc[mi][ni], af[mi][0], af[mi][1], af[mi][2], af[mi][3],
                             bf[ni >> 1][ni & 1], bf[ni >> 1][2 + (ni & 1)]);
        }
        __syncthreads();
    }

    // epilogue
    #pragma unroll
    for (int mi = 0; mi < 4; mi++) {
        #pragma unroll
        for (int half = 0; half < 2; half++) {
            int r = by * 128 + wm + mi * 16 + gr + half * 8;
            size_t rowbase = (size_t)r * N + (size_t)bx * 128;
            #pragma unroll
            for (int ni = 0; ni < 4; ni++) {
                int c = wn + ni * 8 + gc * 2;
                float v0 = acc[mi][ni][half * 2 + 0];
                float v1 = acc[mi][ni][half * 2 + 1];
                if (EPI == EPI_BIAS || EPI == EPI_BIAS_GELU || EPI == EPI_BIAS_RES) {
                    v0 += bias[bx * 128 + c];
                    v1 += bias[bx * 128 + c + 1];
                }
                if (EPI == EPI_BIAS_GELU) {
                    v0 = to_tf32(gelu_exact(v0));    // feeds next GEMM only
                    v1 = to_tf32(gelu_exact(v1));
                }
                if (EPI == EPI_RES || EPI == EPI_BIAS_RES) {
                    v0 += res[rowbase + c];
                    v1 += res[rowbase + c + 1];
                }
                *reinterpret_cast<float2*>(&C[rowbase + c]) = make_float2(v0, v1);
            }
        }
    }
}

// ---------------------------------------------------------------------------
// Split-K reduce: out = p0 + p1 + bias + res (float4, N=1024 -> bias idx i&255)
// ---------------------------------------------------------------------------
__global__ void reduce_bias_res(
    const float4* __restrict__ p0, const float4* __restrict__ p1,
    const float4* __restrict__ bias, const float4* __restrict__ res,
    float4* __restrict__ out)
{
    int i = blockIdx.x * blockDim.x + threadIdx.x;   // 1M float4
    float4 a = p0[i], b = p1[i], c = bias[i & 255], d = res[i];
    out[i] = make_float4(a.x + b.x + c.x + d.x,
                         a.y + b.y + c.y + d.y,
                         a.z + b.z + c.z + d.z,
                         a.w + b.w + c.w + d.w);
}

// ---------------------------------------------------------------------------
// Block reduce (256 threads = 8 warps)
// ---------------------------------------------------------------------------
__device__ __forceinline__ float blockReduceSum256(float v)
{
    __shared__ float sh[8];
    int lane = threadIdx.x & 31;
    int wid  = threadIdx.x >> 5;
    #pragma unroll
    for (int o = 16; o; o >>= 1) v += __shfl_xor_sync(0xffffffffu, v, o);
    __syncthreads();
    if (lane == 0) sh[wid] = v;
    __syncthreads();
    float s = 0.0f;
    #pragma unroll
    for (int i = 0; i < 8; i++) s += sh[i];
    return s;
}

// ---------------------------------------------------------------------------
// AdaLN (output tf32-rounded). gb row layout [g1|b1|g2|b2], stride 4096;
// `off` selects which gamma/beta pair (0 or 2048).
// ---------------------------------------------------------------------------
__global__ __launch_bounds__(256) void adaln_kernel(
    const float* __restrict__ x, const float* __restrict__ gb, int off,
    float* __restrict__ h)
{
    int row = blockIdx.x;
    int t   = threadIdx.x;
    const float* xr = x + (size_t)row * 1024;

    float4 v = *reinterpret_cast<const float4*>(xr + t * 4);
    float s = v.x + v.y + v.z + v.w;
    s = blockReduceSum256(s);
    float mu = s * (1.0f / 1024.0f);

    float dx = v.x - mu, dy = v.y - mu, dz = v.z - mu, dw = v.w - mu;
    float s2 = dx * dx + dy * dy + dz * dz + dw * dw;
    s2 = blockReduceSum256(s2);
    float rstd = rsqrtf(s2 * (1.0f / 1024.0f) + 1e-5f);

    const float* gbr = gb + (size_t)row * 4096 + off;
    float4 g = *reinterpret_cast<const float4*>(gbr + t * 4);
    float4 b = *reinterpret_cast<const float4*>(gbr + 1024 + t * 4);

    float4 o;
    o.x = to_tf32(dx * rstd * (1.0f + g.x) + b.x);
    o.y = to_tf32(dy * rstd * (1.0f + g.y) + b.y);
    o.z = to_tf32(dz * rstd * (1.0f + g.z) + b.z);
    o.w = to_tf32(dw * rstd * (1.0f + g.w) + b.w);
    *reinterpret_cast<float4*>(h + (size_t)row * 1024 + t * 4) = o;
}

// ---------------------------------------------------------------------------
// Tensor-core flash attention (tf32 HMMA). Q-tile 128, KV-tile 64, 8 warps.
// Output tf32-rounded (feeds attn_out GEMM only).
// ---------------------------------------------------------------------------
#define QS_STRIDE 68
#define VT_STRIDE 69
#define ATTN_SMEM_FLOATS (128 * 68 + 64 * 68 + 64 * 69 + 128 * 68)
#define ATTN_SMEM_BYTES  (ATTN_SMEM_FLOATS * 4)

__global__ __launch_bounds__(256) void attn_kernel(
    const float* __restrict__ qkv, float* __restrict__ out)
{
    extern __shared__ float sm[];
    float (*Qs)[QS_STRIDE] = (float(*)[QS_STRIDE])(sm);
    float (*Ks)[QS_STRIDE] = (float(*)[QS_STRIDE])(sm + 128 * 68);
    float (*Vt)[VT_STRIDE] = (float(*)[VT_STRIDE])(sm + 128 * 68 + 64 * 68);
    float (*Ps)[QS_STRIDE] = (float(*)[QS_STRIDE])(sm + 128 * 68 + 64 * 68 + 64 * 69);

    const int qt  = blockIdx.x;
    const int bh  = blockIdx.y;
    const int b   = bh >> 4;
    const int hd  = bh & 15;
    const int tok0 = b * 2048;
    const int qb = hd * 64, kb = 1024 + hd * 64, vb = 2048 + hd * 64;

    const int tid  = threadIdx.x;
    const int lane = tid & 31;
    const int wid  = tid >> 5;
    const int wm   = wid * 16;
    const int gr   = lane >> 2;
    const int gc   = lane & 3;

    const int lr = tid >> 4;
    const int lc = (tid & 15) * 4;

    #pragma unroll
    for (int s = 0; s < 8; s++) {
        int r = lr + s * 16;
        float4 v = *reinterpret_cast<const float4*>(
            &qkv[(size_t)(tok0 + qt * 128 + r) * 3072 + qb + lc]);
        Qs[r][lc + 0] = to_tf32(0.125f * v.x);
        Qs[r][lc + 1] = to_tf32(0.125f * v.y);
        Qs[r][lc + 2] = to_tf32(0.125f * v.z);
        Qs[r][lc + 3] = to_tf32(0.125f * v.w);
    }

    float4 kr4[4], vr4[4];
    #pragma unroll
    for (int s = 0; s < 4; s++) {
        size_t base = (size_t)(tok0 + lr + s * 16) * 3072;
        kr4[s] = *reinterpret_cast<const float4*>(&qkv[base + kb + lc]);
        vr4[s] = *reinterpret_cast<const float4*>(&qkv[base + vb + lc]);
    }

    float m0 = -1e30f, m1 = -1e30f, l0 = 0.0f, l1 = 0.0f;
    float o[8][4];
    #pragma unroll
    for (int nt = 0; nt < 8; nt++)
        #pragma unroll
        for (int q = 0; q < 4; q++) o[nt][q] = 0.0f;

    for (int kt = 0; kt < 32; kt++) {
        #pragma unroll
        for (int s = 0; s < 4; s++) {
            int r = lr + s * 16;
            Ks[r][lc + 0] = to_tf32(kr4[s].x);
            Ks[r][lc + 1] = to_tf32(kr4[s].y);
            Ks[r][lc + 2] = to_tf32(kr4[s].z);
            Ks[r][lc + 3] = to_tf32(kr4[s].w);
            Vt[lc + 0][r] = to_tf32(vr4[s].x);
            Vt[lc + 1][r] = to_tf32(vr4[s].y);
            Vt[lc + 2][r] = to_tf32(vr4[s].z);
            Vt[lc + 3][r] = to_tf32(vr4[s].w);
        }
        __syncthreads();

        if (kt + 1 < 32) {
            #pragma unroll
            for (int s = 0; s < 4; s++) {
                size_t base = (size_t)(tok0 + (kt + 1) * 64 + lr + s * 16) * 3072;
                kr4[s] = *reinterpret_cast<const float4*>(&qkv[base + kb + lc]);
                vr4[s] = *reinterpret_cast<const float4*>(&qkv[base + vb + lc]);
            }
        }

        float sacc[8][4];
        #pragma unroll
        for (int nt = 0; nt < 8; nt++)
            #pragma unroll
            for (int q = 0; q < 4; q++) sacc[nt][q] = 0.0f;

        #pragma unroll
        for (int k8 = 0; k8 < 64; k8 += 8) {
            uint32_t a0 = __float_as_uint(Qs[wm + gr    ][k8 + gc]);
            uint32_t a1 = __float_as_uint(Qs[wm + gr + 8][k8 + gc]);
            uint32_t a2 = __float_as_uint(Qs[wm + gr    ][k8 + gc + 4]);
            uint32_t a3 = __float_as_uint(Qs[wm + gr + 8][k8 + gc + 4]);
            #pragma unroll
            for (int nt = 0; nt < 8; nt++) {
                uint32_t b0 = __float_as_uint(Ks[nt * 8 + gr][k8 + gc]);
                uint32_t b1 = __float_as_uint(Ks[nt * 8 + gr][k8 + gc + 4]);
                mma_tf32(sacc[nt], a0, a1, a2, a3, b0, b1);
            }
        }

        float rm0 = -1e30f, rm1 = -1e30f;
        #pragma unroll
        for (int nt = 0; nt < 8; nt++) {
            rm0 = fmaxf(rm0, fmaxf(sacc[nt][0], sacc[nt][1]));
            rm1 = fmaxf(rm1, fmaxf(sacc[nt][2], sacc[nt][3]));
        }
        rm0 = fmaxf(rm0, __shfl_xor_sync(0xffffffffu, rm0, 1));
        rm0 = fmaxf(rm0, __shfl_xor_sync(0xffffffffu, rm0, 2));
        rm1 = fmaxf(rm1, __shfl_xor_sync(0xffffffffu, rm1, 1));
        rm1 = fmaxf(rm1, __shfl_xor_sync(0xffffffffu, rm1, 2));

        float mn0 = fmaxf(m0, rm0);
        float mn1 = fmaxf(m1, rm1);
        float al0 = __expf(m0 - mn0);
        float al1 = __expf(m1 - mn1);
        m0 = mn0; m1 = mn1;

        float sum0 = 0.0f, sum1 = 0.0f;
        #pragma unroll
        for (int nt = 0; nt < 8; nt++) {
            float p0 = __expf(sacc[nt][0] - mn0);
            float p1 = __expf(sacc[nt][1] - mn0);
            float p2 = __expf(sacc[nt][2] - mn1);
            float p3 = __expf(sacc[nt][3] - mn1);
            sum0 += p0 + p1;
            sum1 += p2 + p3;
            *reinterpret_cast<float2*>(&Ps[wm + gr    ][nt * 8 + 2 * gc]) =
                make_float2(to_tf32(p0), to_tf32(p1));
            *reinterpret_cast<float2*>(&Ps[wm + gr + 8][nt * 8 + 2 * gc]) =
                make_float2(to_tf32(p2), to_tf32(p3));
        }
        sum0 += __shfl_xor_sync(0xffffffffu, sum0, 1);
        sum0 += __shfl_xor_sync(0xffffffffu, sum0, 2);
        sum1 += __shfl_xor_sync(0xffffffffu, sum1, 1);
        sum1 += __shfl_xor_sync(0xffffffffu, sum1, 2);
        l0 = l0 * al0 + sum0;
        l1 = l1 * al1 + sum1;

        #pragma unroll
        for (int nt = 0; nt < 8; nt++) {
            o[nt][0] *= al0; o[nt][1] *= al0;
            o[nt][2] *= al1; o[nt][3] *= al1;
        }
        __syncwarp();

        #pragma unroll
        for (int k8 = 0; k8 < 64; k8 += 8) {
            uint32_t a0 = __float_as_uint(Ps[wm + gr    ][k8 + gc]);
            uint32_t a1 = __float_as_uint(Ps[wm + gr + 8][k8 + gc]);
            uint32_t a2 = __float_as_uint(Ps[wm + gr    ][k8 + gc + 4]);
            uint32_t a3 = __float_as_uint(Ps[wm + gr + 8][k8 + gc + 4]);
            #pragma unroll
            for (int nt = 0; nt < 8; nt++) {
                uint32_t b0 = __float_as_uint(Vt[nt * 8 + gr][k8 + gc]);
                uint32_t b1 = __float_as_uint(Vt[nt * 8 + gr][k8 + gc + 4]);
                mma_tf32(o[nt], a0, a1, a2, a3, b0, b1);
            }
        }
        __syncthreads();
    }

    float inv0 = 1.0f / l0;
    float inv1 = 1.0f / l1;
    int t0 = tok0 + qt * 128 + wm + gr;
    int t1 = t0 + 8;
    #pragma unroll
    for (int nt = 0; nt < 8; nt++) {
        int col = hd * 64 + nt * 8 + 2 * gc;
        *reinterpret_cast<float2*>(&out[(size_t)t0 * 1024 + col]) =
            make_float2(to_tf32(o[nt][0] * inv0), to_tf32(o[nt][1] * inv0));
        *reinterpret_cast<float2*>(&out[(size_t)t1 * 1024 + col]) =
            make_float2(to_tf32(o[nt][2] * inv1), to_tf32(o[nt][3] * inv1));
    }
}

// ---------------------------------------------------------------------------
// Launch
// ---------------------------------------------------------------------------
extern "C" void kernel_launch(void* const* d_in, const int* in_sizes, int n_in,
                              void* d_out, int out_size)
{
    const float* x        = (const float*)d_in[0];
    const float* cond     = (const float*)d_in[1];
    const float* p1_w     = (const float*)d_in[2];
    const float* p1_b     = (const float*)d_in[3];
    const float* qkv_w    = (const float*)d_in[4];
    const float* attn_o_w = (const float*)d_in[5];
    const float* p2_w     = (const float*)d_in[6];
    const float* p2_b     = (const float*)d_in[7];
    const float* ffn_w1   = (const float*)d_in[8];
    const float* ffn_b1   = (const float*)d_in[9];
    const float* ffn_w2   = (const float*)d_in[10];
    const float* ffn_b2   = (const float*)d_in[11];
    float* out = (float*)d_out;

    float *sc, *gb12, *h, *qkvp, *attn, *x2, *h2, *ff, *pk;
    float *wgb, *bgb, *wqkv, *wao, *wf1, *wf2;
    cudaGetSymbolAddress((void**)&sc,   g_sc);
    cudaGetSymbolAddress((void**)&gb12, g_gb12);
    cudaGetSymbolAddress((void**)&h,    g_h);
    cudaGetSymbolAddress((void**)&qkvp, g_qkv);
    cudaGetSymbolAddress((void**)&attn, g_attn);
    cudaGetSymbolAddress((void**)&x2,   g_x2);
    cudaGetSymbolAddress((void**)&h2,   g_h2);
    cudaGetSymbolAddress((void**)&ff,   g_ff);
    cudaGetSymbolAddress((void**)&pk,   g_pk);
    cudaGetSymbolAddress((void**)&wgb,  g_wgb);
    cudaGetSymbolAddress((void**)&bgb,  g_bgb);
    cudaGetSymbolAddress((void**)&wqkv, g_wqkv);
    cudaGetSymbolAddress((void**)&wao,  g_wao);
    cudaGetSymbolAddress((void**)&wf1,  g_wf1);
    cudaGetSymbolAddress((void**)&wf2,  g_wf2);

    static int attr_done = 0;
    if (!attr_done) {
        cudaFuncSetAttribute(attn_kernel, cudaFuncAttributeMaxDynamicSharedMemorySize, ATTN_SMEM_BYTES);
        cudaFuncSetAttribute(tf32gemm<EPI_NONE>,      cudaFuncAttributeMaxDynamicSharedMemorySize, GEMM_SMEM_BYTES);
        cudaFuncSetAttribute(tf32gemm<EPI_BIAS>,      cudaFuncAttributeMaxDynamicSharedMemorySize, GEMM_SMEM_BYTES);
        cudaFuncSetAttribute(tf32gemm<EPI_BIAS_GELU>, cudaFuncAttributeMaxDynamicSharedMemorySize, GEMM_SMEM_BYTES);
        cudaFuncSetAttribute(tf32gemm<EPI_RES>,       cudaFuncAttributeMaxDynamicSharedMemorySize, GEMM_SMEM_BYTES);
        cudaFuncSetAttribute(tf32gemm<EPI_BIAS_RES>,  cudaFuncAttributeMaxDynamicSharedMemorySize, GEMM_SMEM_BYTES);
        attr_done = 1;
    }

    // 0) prologue: weight cvt+transpose + silu + bias concat (ONE launch)
    prologue_all<<<16388, 256>>>(
        p1_w, p2_w, qkv_w, attn_o_w, ffn_w1, ffn_w2,
        (const float4*)cond, (const float4*)p1_b, (const float4*)p2_b,
        wgb, wqkv, wao, wf1, wf2, (float4*)sc, (float4*)bgb);

    // 1) gb12 = sc @ [p1_w|p2_w] + [p1_b|p2_b]   (4096x512 @ 512x4096, FUSED)
    tf32gemm<EPI_BIAS><<<dim3(32, 32), 256, GEMM_SMEM_BYTES>>>(
        sc, wgb, gb12, T_TOK, 4096, 512, 512, bgb, nullptr);

    // 2) h = tf32(adaln(x, gamma1/beta1))
    adaln_kernel<<<T_TOK, 256>>>(x, gb12, 0, h);

    // 3) qkv = h @ qkv_w  (4096x1024 @ 1024x3072)
    tf32gemm<EPI_NONE><<<dim3(24, 32), 256, GEMM_SMEM_BYTES>>>(
        h, wqkv, qkvp, T_TOK, 3072, 1024, 1024, nullptr, nullptr);

    // 4) attention (HMMA tensor cores)
    attn_kernel<<<dim3(16, 32), 256, ATTN_SMEM_BYTES>>>(qkvp, attn);

    // 5) x2 = x + attn @ attn_out_w  (4096x1024 @ 1024x1024)
    tf32gemm<EPI_RES><<<dim3(8, 32), 256, GEMM_SMEM_BYTES>>>(
        attn, wao, x2, T_TOK, 1024, 1024, 1024, nullptr, x);

    // 6) h2 = tf32(adaln(x2, gamma2/beta2))
    adaln_kernel<<<T_TOK, 256>>>(x2, gb12, 2048, h2);

    // 7) ff = tf32(gelu(h2 @ ffn_w1 + b1))  (4096x1024 @ 1024x4096)
    tf32gemm<EPI_BIAS_GELU><<<dim3(32, 32), 256, GEMM_SMEM_BYTES>>>(
        h2, wf1, ff, T_TOK, 4096, 1024, 1024, ffn_b1, nullptr);

    // 8) f2 split-K x2: pk[z] = ff[:, z*2048:(z+1)*2048] @ wf2-chunk (grid z=2)
    tf32gemm<EPI_NONE><<<dim3(8, 32, 2), 256, GEMM_SMEM_BYTES>>>(
        ff, wf2, pk, T_TOK, 1024, 4096, 2048, nullptr, nullptr);

    // 9) out = pk0 + pk1 + b2 + x2
    reduce_bias_res<<<4096, 256>>>(
        (const float4*)pk, (const float4*)(pk + (size_t)T_TOK * 1024),
        (const float4*)ffn_b2, (const float4*)x2, (float4*)out);
}

// round 13
// speedup vs baseline: 1.0016x; 1.0016x over previous
#include <cuda_runtime.h>
#include <math.h>
#include <stdint.h>

// ---------------------------------------------------------------------------
// DecoderBlock (DiT-style): AdaLN -> MHA -> residual -> AdaLN -> FFN -> residual
// B=2, S=2048 (T=4096 tokens), D=1024, H=16, d=64, D_COND=512, FF=4096, fp32.
// tf32 HMMA (tcgen05 unavailable on this toolchain). Weights pre-rounded tf32
// + pre-transposed [N][K]; ldmatrix.x4 frags; BK=16, 4-stage cp.async ring,
// 2 CTA/SM. Fused gb GEMM; split-K x2 for f2. Weight cvt for the 4 late
// GEMMs runs on a FORKED side stream overlapped with the gb GEMM.
// ---------------------------------------------------------------------------

#define T_TOK 4096

__device__ float g_sc  [T_TOK * 512];
__device__ float g_gb12[T_TOK * 4096];   // fused [gamma1|beta1|gamma2|beta2]
__device__ float g_h   [T_TOK * 1024];
__device__ float g_qkv [T_TOK * 3072];
__device__ float g_attn[T_TOK * 1024];
__device__ float g_x2  [T_TOK * 1024];
__device__ float g_h2  [T_TOK * 1024];
__device__ float g_ff  [T_TOK * 4096];
__device__ float g_pk  [2 * T_TOK * 1024];   // f2 split-K partials
// tf32-rounded, TRANSPOSED ([N][K]) weight copies
__device__ float g_wgb [4096 * 512];     // rows 0-2047: p1_w^T, rows 2048-4095: p2_w^T
__device__ float g_bgb [4096];           // p1_b | p2_b
__device__ float g_wqkv[3072 * 1024];
__device__ float g_wao [1024 * 1024];
__device__ float g_wf1 [4096 * 1024];
__device__ float g_wf2 [1024 * 4096];

enum { EPI_NONE = 0, EPI_BIAS = 1, EPI_BIAS_GELU = 2, EPI_RES = 3, EPI_BIAS_RES = 4 };

__device__ __forceinline__ float gelu_exact(float v) {
    return 0.5f * v * (1.0f + erff(v * 0.70710678118654752440f));
}

__device__ __forceinline__ float to_tf32(float x) {
    uint32_t u;
    asm("cvt.rna.tf32.f32 %0, %1;" : "=r"(u) : "f"(x));
    return __uint_as_float(u);
}

__device__ __forceinline__ void mma_tf32(float* c,
    uint32_t a0, uint32_t a1, uint32_t a2, uint32_t a3, uint32_t b0, uint32_t b1)
{
    asm volatile(
        "mma.sync.aligned.m16n8k8.row.col.f32.tf32.tf32.f32 "
        "{%0,%1,%2,%3},{%4,%5,%6,%7},{%8,%9},{%0,%1,%2,%3};\n"
        : "+f"(c[0]), "+f"(c[1]), "+f"(c[2]), "+f"(c[3])
        : "r"(a0), "r"(a1), "r"(a2), "r"(a3), "r"(b0), "r"(b1));
}

__device__ __forceinline__ void ldsm_x4(uint32_t* r, uint32_t saddr) {
    asm volatile("ldmatrix.sync.aligned.m8n8.x4.shared.b16 {%0,%1,%2,%3}, [%4];"
                 : "=r"(r[0]), "=r"(r[1]), "=r"(r[2]), "=r"(r[3]) : "r"(saddr));
}

__device__ __forceinline__ void cp16(float* smem_dst, const float* gsrc) {
    uint32_t d = (uint32_t)__cvta_generic_to_shared(smem_dst);
    asm volatile("cp.async.cg.shared.global [%0], [%1], 16;\n" :: "r"(d), "l"(gsrc));
}
__device__ __forceinline__ void cp_commit() {
    asm volatile("cp.async.commit_group;\n");
}
template <int N>
__device__ __forceinline__ void cp_wait() {
    asm volatile("cp.async.wait_group %0;\n" :: "n"(N));
}

// ---------------------------------------------------------------------------
// cvt+transpose tile body (32x32 via smem): dst[N][K] = tf32(src[K][N]^T)
// ---------------------------------------------------------------------------
__device__ __forceinline__ void cvt_tile(
    const float* __restrict__ src, float* __restrict__ dst,
    int K, int N, int tile, int tid)
{
    __shared__ float t[32][33];
    const int ntx = N >> 5;
    const int n0 = (tile % ntx) * 32;
    const int k0 = (tile / ntx) * 32;
    const int tx = tid & 31;
    const int ty = tid >> 5;
    #pragma unroll
    for (int i = 0; i < 32; i += 8)
        t[ty + i][tx] = to_tf32(src[(size_t)(k0 + ty + i) * N + n0 + tx]);
    __syncthreads();
    #pragma unroll
    for (int i = 0; i < 32; i += 8)
        dst[(size_t)(n0 + ty + i) * K + k0 + tx] = t[tx][ty + i];
}

// Main-stream prologue: p1/p2 cvt (2048 tiles) + silu (2048) + bias (4)
__global__ __launch_bounds__(256) void prologue_main(
    const float* __restrict__ p1, const float* __restrict__ p2,
    const float4* __restrict__ cond,
    const float4* __restrict__ b1, const float4* __restrict__ b2,
    float* __restrict__ ogb, float4* __restrict__ sc, float4* __restrict__ bgb)
{
    int blk = blockIdx.x;
    int tid = threadIdx.x;
    if (blk < 1024) {
        cvt_tile(p1, ogb, 512, 2048, blk, tid);
    } else if (blk < 2048) {
        cvt_tile(p2, ogb + 2048 * 512, 512, 2048, blk - 1024, tid);
    } else if (blk < 4096) {
        int i = (blk - 2048) * 256 + tid;
        float4 v = cond[i];
        sc[i] = make_float4(
            to_tf32(v.x / (1.0f + __expf(-v.x))),
            to_tf32(v.y / (1.0f + __expf(-v.y))),
            to_tf32(v.z / (1.0f + __expf(-v.z))),
            to_tf32(v.w / (1.0f + __expf(-v.w))));
    } else {
        int i = (blk - 4096) * 256 + tid;
        bgb[i] = (i < 512) ? b1[i] : b2[i - 512];
    }
}

// Side-stream prologue: qkv/ao/f1/f2 cvt (12288 tiles), overlapped with gb GEMM
__global__ __launch_bounds__(256) void prologue_side(
    const float* __restrict__ qk, const float* __restrict__ ao,
    const float* __restrict__ f1, const float* __restrict__ f2,
    float* __restrict__ oq, float* __restrict__ oa,
    float* __restrict__ of1, float* __restrict__ of2)
{
    int blk = blockIdx.x;
    int tid = threadIdx.x;
    if      (blk < 3072)  cvt_tile(qk, oq,  1024, 3072, blk, tid);
    else if (blk < 4096)  cvt_tile(ao, oa,  1024, 1024, blk - 3072, tid);
    else if (blk < 8192)  cvt_tile(f1, of1, 1024, 4096, blk - 4096, tid);
    else                  cvt_tile(f2, of2, 4096, 1024, blk - 8192, tid);
}

// ---------------------------------------------------------------------------
// tf32 GEMM: C(MxN) = A(MxK) @ Bt(NxK)^T [+bias][+gelu][+res]
// Block 128x128, BK=16, 256 threads (8 warps, 2x4), warp tile 64x32.
// Split-K via blockIdx.z: z-th chunk of Klen columns, C += z*M*N.
// 4-stage cp.async ring, ldmatrix.x4 frags, 2 CTAs/SM.
// ---------------------------------------------------------------------------
#define GST (128 * 20)
#define GSS (2 * GST)
#define GEMM_STAGES 4
#define GEMM_SMEM_BYTES (GEMM_STAGES * GSS * 4)

template <int EPI>
__global__ __launch_bounds__(256, 2) void tf32gemm(
    const float* __restrict__ A, const float* __restrict__ Bt, float* __restrict__ C,
    int M, int N, int Kstride, int Klen,
    const float* __restrict__ bias, const float* __restrict__ res)
{
    extern __shared__ float sm[];

    const int tid  = threadIdx.x;
    const int bx   = blockIdx.x;
    const int by   = blockIdx.y;
    const int kz   = blockIdx.z;
    const int lane = tid & 31;
    const int wid  = tid >> 5;
    const int wm   = (wid >> 2) * 64;
    const int wn   = (wid & 3) * 32;
    const int gr   = lane >> 2;
    const int gc   = lane & 3;

    const int rowsel = (lane & 7) + ((lane >> 3) & 1) * 8;
    const int kadd   = (lane >> 4) * 4;

    const int srow = tid >> 1;
    const int scol = (tid & 1) * 8;
    const size_t koff = (size_t)kz * Klen;
    const float* Agb = A  + (size_t)(by * 128 + srow) * Kstride + koff + scol;
    const float* Bgb = Bt + (size_t)(bx * 128 + srow) * Kstride + koff + scol;
    C += (size_t)kz * M * N;

    const int nk = Klen >> 4;

    float acc[4][4][4];
    #pragma unroll
    for (int mi = 0; mi < 4; mi++)
        #pragma unroll
        for (int ni = 0; ni < 4; ni++)
            #pragma unroll
            for (int q = 0; q < 4; q++) acc[mi][ni][q] = 0.0f;

    #pragma unroll
    for (int s = 0; s < GEMM_STAGES - 1; s++) {
        float* as = sm + s * GSS;
        float* bs = as + GST;
        cp16(as + srow * 20 + scol,     Agb + s * 16);
        cp16(as + srow * 20 + scol + 4, Agb + s * 16 + 4);
        cp16(bs + srow * 20 + scol,     Bgb + s * 16);
        cp16(bs + srow * 20 + scol + 4, Bgb + s * 16 + 4);
        cp_commit();
    }

    const uint32_t smemBase = (uint32_t)__cvta_generic_to_shared(sm);

    for (int kt = 0; kt < nk; kt++) {
        cp_wait<GEMM_STAGES - 2>();
        __syncthreads();

        if (kt + GEMM_STAGES - 1 < nk) {
            int s = (kt + GEMM_STAGES - 1) % GEMM_STAGES;
            float* as = sm + s * GSS;
            float* bs = as + GST;
            cp16(as + srow * 20 + scol,     Agb + (kt + GEMM_STAGES - 1) * 16);
            cp16(as + srow * 20 + scol + 4, Agb + (kt + GEMM_STAGES - 1) * 16 + 4);
            cp16(bs + srow * 20 + scol,     Bgb + (size_t)(kt + GEMM_STAGES - 1) * 16);
            cp16(bs + srow * 20 + scol + 4, Bgb + (size_t)(kt + GEMM_STAGES - 1) * 16 + 4);
        }
        cp_commit();

        const uint32_t asAddr = smemBase + ((kt % GEMM_STAGES) * GSS) * 4;
        const uint32_t bsAddr = asAddr + GST * 4;
        const uint32_t aBase = asAddr + ((wm + rowsel) * 20 + kadd) * 4;
        const uint32_t bBase = bsAddr + ((wn + rowsel) * 20 + kadd) * 4;

        #pragma unroll
        for (int k8 = 0; k8 < 16; k8 += 8) {
            uint32_t af[4][4], bf[2][4];
            #pragma unroll
            for (int mi = 0; mi < 4; mi++)
                ldsm_x4(af[mi], aBase + (mi * 16 * 20 + k8) * 4);
            #pragma unroll
            for (int p = 0; p < 2; p++)
                ldsm_x4(bf[p], bBase + (p * 16 * 20 + k8) * 4);
            #pragma unroll
            for (int mi = 0; mi < 4; mi++)
                #pragma unroll
                for (int ni = 0; ni < 4; ni++)
                    mma_tf32(acc[mi][ni], af[mi][0], af[mi][1], af[mi][2], af[mi][3],
                             bf[ni >> 1][ni & 1], bf[ni >> 1][2 + (ni & 1)]);
        }
        __syncthreads();
    }

    #pragma unroll
    for (int mi = 0; mi < 4; mi++) {
        #pragma unroll
        for (int half = 0; half < 2; half++) {
            int r = by * 128 + wm + mi * 16 + gr + half * 8;
            size_t rowbase = (size_t)r * N + (size_t)bx * 128;
            #pragma unroll
            for (int ni = 0; ni < 4; ni++) {
                int c = wn + ni * 8 + gc * 2;
                float v0 = acc[mi][ni][half * 2 + 0];
                float v1 = acc[mi][ni][half * 2 + 1];
                if (EPI == EPI_BIAS || EPI == EPI_BIAS_GELU || EPI == EPI_BIAS_RES) {
                    v0 += bias[bx * 128 + c];
                    v1 += bias[bx * 128 + c + 1];
                }
                if (EPI == EPI_BIAS_GELU) {
                    v0 = to_tf32(gelu_exact(v0));
                    v1 = to_tf32(gelu_exact(v1));
                }
                if (EPI == EPI_RES || EPI == EPI_BIAS_RES) {
                    v0 += res[rowbase + c];
                    v1 += res[rowbase + c + 1];
                }
                *reinterpret_cast<float2*>(&C[rowbase + c]) = make_float2(v0, v1);
            }
        }
    }
}

// ---------------------------------------------------------------------------
// Split-K reduce: out = p0 + p1 + bias + res
// ---------------------------------------------------------------------------
__global__ void reduce_bias_res(
    const float4* __restrict__ p0, const float4* __restrict__ p1,
    const float4* __restrict__ bias, const float4* __restrict__ res,
    float4* __restrict__ out)
{
    int i = blockIdx.x * blockDim.x + threadIdx.x;
    float4 a = p0[i], b = p1[i], c = bias[i & 255], d = res[i];
    out[i] = make_float4(a.x + b.x + c.x + d.x,
                         a.y + b.y + c.y + d.y,
                         a.z + b.z + c.z + d.z,
                         a.w + b.w + c.w + d.w);
}

// ---------------------------------------------------------------------------
// Block reduce (256 threads = 8 warps)
// ---------------------------------------------------------------------------
__device__ __forceinline__ float blockReduceSum256(float v)
{
    __shared__ float sh[8];
    int lane = threadIdx.x & 31;
    int wid  = threadIdx.x >> 5;
    #pragma unroll
    for (int o = 16; o; o >>= 1) v += __shfl_xor_sync(0xffffffffu, v, o);
    __syncthreads();
    if (lane == 0) sh[wid] = v;
    __syncthreads();
    float s = 0.0f;
    #pragma unroll
    for (int i = 0; i < 8; i++) s += sh[i];
    return s;
}

// ---------------------------------------------------------------------------
// AdaLN (output tf32-rounded). gb row layout [g1|b1|g2|b2], stride 4096.
// ---------------------------------------------------------------------------
__global__ __launch_bounds__(256) void adaln_kernel(
    const float* __restrict__ x, const float* __restrict__ gb, int off,
    float* __restrict__ h)
{
    int row = blockIdx.x;
    int t   = threadIdx.x;
    const float* xr = x + (size_t)row * 1024;

    float4 v = *reinterpret_cast<const float4*>(xr + t * 4);
    float s = v.x + v.y + v.z + v.w;
    s = blockReduceSum256(s);
    float mu = s * (1.0f / 1024.0f);

    float dx = v.x - mu, dy = v.y - mu, dz = v.z - mu, dw = v.w - mu;
    float s2 = dx * dx + dy * dy + dz * dz + dw * dw;
    s2 = blockReduceSum256(s2);
    float rstd = rsqrtf(s2 * (1.0f / 1024.0f) + 1e-5f);

    const float* gbr = gb + (size_t)row * 4096 + off;
    float4 g = *reinterpret_cast<const float4*>(gbr + t * 4);
    float4 b = *reinterpret_cast<const float4*>(gbr + 1024 + t * 4);

    float4 o;
    o.x = to_tf32(dx * rstd * (1.0f + g.x) + b.x);
    o.y = to_tf32(dy * rstd * (1.0f + g.y) + b.y);
    o.z = to_tf32(dz * rstd * (1.0f + g.z) + b.z);
    o.w = to_tf32(dw * rstd * (1.0f + g.w) + b.w);
    *reinterpret_cast<float4*>(h + (size_t)row * 1024 + t * 4) = o;
}

// ---------------------------------------------------------------------------
// Tensor-core flash attention (tf32 HMMA). Q-tile 128, KV-tile 64, 8 warps.
// ---------------------------------------------------------------------------
#define QS_STRIDE 68
#define VT_STRIDE 69
#define ATTN_SMEM_FLOATS (128 * 68 + 64 * 68 + 64 * 69 + 128 * 68)
#define ATTN_SMEM_BYTES  (ATTN_SMEM_FLOATS * 4)

__global__ __launch_bounds__(256) void attn_kernel(
    const float* __restrict__ qkv, float* __restrict__ out)
{
    extern __shared__ float sm[];
    float (*Qs)[QS_STRIDE] = (float(*)[QS_STRIDE])(sm);
    float (*Ks)[QS_STRIDE] = (float(*)[QS_STRIDE])(sm + 128 * 68);
    float (*Vt)[VT_STRIDE] = (float(*)[VT_STRIDE])(sm + 128 * 68 + 64 * 68);
    float (*Ps)[QS_STRIDE] = (float(*)[QS_STRIDE])(sm + 128 * 68 + 64 * 68 + 64 * 69);

    const int qt  = blockIdx.x;
    const int bh  = blockIdx.y;
    const int b   = bh >> 4;
    const int hd  = bh & 15;
    const int tok0 = b * 2048;
    const int qb = hd * 64, kb = 1024 + hd * 64, vb = 2048 + hd * 64;

    const int tid  = threadIdx.x;
    const int lane = tid & 31;
    const int wid  = tid >> 5;
    const int wm   = wid * 16;
    const int gr   = lane >> 2;
    const int gc   = lane & 3;

    const int lr = tid >> 4;
    const int lc = (tid & 15) * 4;

    #pragma unroll
    for (int s = 0; s < 8; s++) {
        int r = lr + s * 16;
        float4 v = *reinterpret_cast<const float4*>(
            &qkv[(size_t)(tok0 + qt * 128 + r) * 3072 + qb + lc]);
        Qs[r][lc + 0] = to_tf32(0.125f * v.x);
        Qs[r][lc + 1] = to_tf32(0.125f * v.y);
        Qs[r][lc + 2] = to_tf32(0.125f * v.z);
        Qs[r][lc + 3] = to_tf32(0.125f * v.w);
    }

    float4 kr4[4], vr4[4];
    #pragma unroll
    for (int s = 0; s < 4; s++) {
        size_t base = (size_t)(tok0 + lr + s * 16) * 3072;
        kr4[s] = *reinterpret_cast<const float4*>(&qkv[base + kb + lc]);
        vr4[s] = *reinterpret_cast<const float4*>(&qkv[base + vb + lc]);
    }

    float m0 = -1e30f, m1 = -1e30f, l0 = 0.0f, l1 = 0.0f;
    float o[8][4];
    #pragma unroll
    for (int nt = 0; nt < 8; nt++)
        #pragma unroll
        for (int q = 0; q < 4; q++) o[nt][q] = 0.0f;

    for (int kt = 0; kt < 32; kt++) {
        #pragma unroll
        for (int s = 0; s < 4; s++) {
            int r = lr + s * 16;
            Ks[r][lc + 0] = to_tf32(kr4[s].x);
            Ks[r][lc + 1] = to_tf32(kr4[s].y);
            Ks[r][lc + 2] = to_tf32(kr4[s].z);
            Ks[r][lc + 3] = to_tf32(kr4[s].w);
            Vt[lc + 0][r] = to_tf32(vr4[s].x);
            Vt[lc + 1][r] = to_tf32(vr4[s].y);
            Vt[lc + 2][r] = to_tf32(vr4[s].z);
            Vt[lc + 3][r] = to_tf32(vr4[s].w);
        }
        __syncthreads();

        if (kt + 1 < 32) {
            #pragma unroll
            for (int s = 0; s < 4; s++) {
                size_t base = (size_t)(tok0 + (kt + 1) * 64 + lr + s * 16) * 3072;
                kr4[s] = *reinterpret_cast<const float4*>(&qkv[base + kb + lc]);
                vr4[s] = *reinterpret_cast<const float4*>(&qkv[base + vb + lc]);
            }
        }

        float sacc[8][4];
        #pragma unroll
        for (int nt = 0; nt < 8; nt++)
            #pragma unroll
            for (int q = 0; q < 4; q++) sacc[nt][q] = 0.0f;

        #pragma unroll
        for (int k8 = 0; k8 < 64; k8 += 8) {
            uint32_t a0 = __float_as_uint(Qs[wm + gr    ][k8 + gc]);
            uint32_t a1 = __float_as_uint(Qs[wm + gr + 8][k8 + gc]);
            uint32_t a2 = __float_as_uint(Qs[wm + gr    ][k8 + gc + 4]);
            uint32_t a3 = __float_as_uint(Qs[wm + gr + 8][k8 + gc + 4]);
            #pragma unroll
            for (int nt = 0; nt < 8; nt++) {
                uint32_t b0 = __float_as_uint(Ks[nt * 8 + gr][k8 + gc]);
                uint32_t b1 = __float_as_uint(Ks[nt * 8 + gr][k8 + gc + 4]);
                mma_tf32(sacc[nt], a0, a1, a2, a3, b0, b1);
            }
        }

        float rm0 = -1e30f, rm1 = -1e30f;
        #pragma unroll
        for (int nt = 0; nt < 8; nt++) {
            rm0 = fmaxf(rm0, fmaxf(sacc[nt][0], sacc[nt][1]));
            rm1 = fmaxf(rm1, fmaxf(sacc[nt][2], sacc[nt][3]));
        }
        rm0 = fmaxf(rm0, __shfl_xor_sync(0xffffffffu, rm0, 1));
        rm0 = fmaxf(rm0, __shfl_xor_sync(0xffffffffu, rm0, 2));
        rm1 = fmaxf(rm1, __shfl_xor_sync(0xffffffffu, rm1, 1));
        rm1 = fmaxf(rm1, __shfl_xor_sync(0xffffffffu, rm1, 2));

        float mn0 = fmaxf(m0, rm0);
        float mn1 = fmaxf(m1, rm1);
        float al0 = __expf(m0 - mn0);
        float al1 = __expf(m1 - mn1);
        m0 = mn0; m1 = mn1;

        float sum0 = 0.0f, sum1 = 0.0f;
        #pragma unroll
        for (int nt = 0; nt < 8; nt++) {
            float p0 = __expf(sacc[nt][0] - mn0);
            float p1 = __expf(sacc[nt][1] - mn0);
            float p2 = __expf(sacc[nt][2] - mn1);
            float p3 = __expf(sacc[nt][3] - mn1);
            sum0 += p0 + p1;
            sum1 += p2 + p3;
            *reinterpret_cast<float2*>(&Ps[wm + gr    ][nt * 8 + 2 * gc]) =
                make_float2(to_tf32(p0), to_tf32(p1));
            *reinterpret_cast<float2*>(&Ps[wm + gr + 8][nt * 8 + 2 * gc]) =
                make_float2(to_tf32(p2), to_tf32(p3));
        }
        sum0 += __shfl_xor_sync(0xffffffffu, sum0, 1);
        sum0 += __shfl_xor_sync(0xffffffffu, sum0, 2);
        sum1 += __shfl_xor_sync(0xffffffffu, sum1, 1);
        sum1 += __shfl_xor_sync(0xffffffffu, sum1, 2);
        l0 = l0 * al0 + sum0;
        l1 = l1 * al1 + sum1;

        #pragma unroll
        for (int nt = 0; nt < 8; nt++) {
            o[nt][0] *= al0; o[nt][1] *= al0;
            o[nt][2] *= al1; o[nt][3] *= al1;
        }
        __syncwarp();

        #pragma unroll
        for (int k8 = 0; k8 < 64; k8 += 8) {
            uint32_t a0 = __float_as_uint(Ps[wm + gr    ][k8 + gc]);
            uint32_t a1 = __float_as_uint(Ps[wm + gr + 8][k8 + gc]);
            uint32_t a2 = __float_as_uint(Ps[wm + gr    ][k8 + gc + 4]);
            uint32_t a3 = __float_as_uint(Ps[wm + gr + 8][k8 + gc + 4]);
            #pragma unroll
            for (int nt = 0; nt < 8; nt++) {
                uint32_t b0 = __float_as_uint(Vt[nt * 8 + gr][k8 + gc]);
                uint32_t b1 = __float_as_uint(Vt[nt * 8 + gr][k8 + gc + 4]);
                mma_tf32(o[nt], a0, a1, a2, a3, b0, b1);
            }
        }
        __syncthreads();
    }

    float inv0 = 1.0f / l0;
    float inv1 = 1.0f / l1;
    int t0 = tok0 + qt * 128 + wm + gr;
    int t1 = t0 + 8;
    #pragma unroll
    for (int nt = 0; nt < 8; nt++) {
        int col = hd * 64 + nt * 8 + 2 * gc;
        *reinterpret_cast<float2*>(&out[(size_t)t0 * 1024 + col]) =
            make_float2(to_tf32(o[nt][0] * inv0), to_tf32(o[nt][1] * inv0));
        *reinterpret_cast<float2*>(&out[(size_t)t1 * 1024 + col]) =
            make_float2(to_tf32(o[nt][2] * inv1), to_tf32(o[nt][3] * inv1));
    }
}

// ---------------------------------------------------------------------------
// Launch
// ---------------------------------------------------------------------------
extern "C" void kernel_launch(void* const* d_in, const int* in_sizes, int n_in,
                              void* d_out, int out_size)
{
    const float* x        = (const float*)d_in[0];
    const float* cond     = (const float*)d_in[1];
    const float* p1_w     = (const float*)d_in[2];
    const float* p1_b     = (const float*)d_in[3];
    const float* qkv_w    = (const float*)d_in[4];
    const float* attn_o_w = (const float*)d_in[5];
    const float* p2_w     = (const float*)d_in[6];
    const float* p2_b     = (const float*)d_in[7];
    const float* ffn_w1   = (const float*)d_in[8];
    const float* ffn_b1   = (const float*)d_in[9];
    const float* ffn_w2   = (const float*)d_in[10];
    const float* ffn_b2   = (const float*)d_in[11];
    float* out = (float*)d_out;

    float *sc, *gb12, *h, *qkvp, *attn, *x2, *h2, *ff, *pk;
    float *wgb, *bgb, *wqkv, *wao, *wf1, *wf2;
    cudaGetSymbolAddress((void**)&sc,   g_sc);
    cudaGetSymbolAddress((void**)&gb12, g_gb12);
    cudaGetSymbolAddress((void**)&h,    g_h);
    cudaGetSymbolAddress((void**)&qkvp, g_qkv);
    cudaGetSymbolAddress((void**)&attn, g_attn);
    cudaGetSymbolAddress((void**)&x2,   g_x2);
    cudaGetSymbolAddress((void**)&h2,   g_h2);
    cudaGetSymbolAddress((void**)&ff,   g_ff);
    cudaGetSymbolAddress((void**)&pk,   g_pk);
    cudaGetSymbolAddress((void**)&wgb,  g_wgb);
    cudaGetSymbolAddress((void**)&bgb,  g_bgb);
    cudaGetSymbolAddress((void**)&wqkv, g_wqkv);
    cudaGetSymbolAddress((void**)&wao,  g_wao);
    cudaGetSymbolAddress((void**)&wf1,  g_wf1);
    cudaGetSymbolAddress((void**)&wf2,  g_wf2);

    static cudaStream_t s_side = nullptr;
    static cudaEvent_t  s_ev_fork = nullptr, s_ev_join = nullptr;
    static int attr_done = 0;
    if (!attr_done) {
        cudaFuncSetAttribute(attn_kernel, cudaFuncAttributeMaxDynamicSharedMemorySize, ATTN_SMEM_BYTES);
        cudaFuncSetAttribute(tf32gemm<EPI_NONE>,      cudaFuncAttributeMaxDynamicSharedMemorySize, GEMM_SMEM_BYTES);
        cudaFuncSetAttribute(tf32gemm<EPI_BIAS>,      cudaFuncAttributeMaxDynamicSharedMemorySize, GEMM_SMEM_BYTES);
        cudaFuncSetAttribute(tf32gemm<EPI_BIAS_GELU>, cudaFuncAttributeMaxDynamicSharedMemorySize, GEMM_SMEM_BYTES);
        cudaFuncSetAttribute(tf32gemm<EPI_RES>,       cudaFuncAttributeMaxDynamicSharedMemorySize, GEMM_SMEM_BYTES);
        cudaFuncSetAttribute(tf32gemm<EPI_BIAS_RES>,  cudaFuncAttributeMaxDynamicSharedMemorySize, GEMM_SMEM_BYTES);
        cudaStreamCreateWithFlags(&s_side, cudaStreamNonBlocking);
        cudaEventCreateWithFlags(&s_ev_fork, cudaEventDisableTiming);
        cudaEventCreateWithFlags(&s_ev_join, cudaEventDisableTiming);
        attr_done = 1;
    }

    // ---- fork: side stream converts the 4 late weights, overlapped with gb ----
    cudaEventRecord(s_ev_fork, 0);
    cudaStreamWaitEvent(s_side, s_ev_fork, 0);
    prologue_side<<<12288, 256, 0, s_side>>>(
        qkv_w, attn_o_w, ffn_w1, ffn_w2, wqkv, wao, wf1, wf2);
    cudaEventRecord(s_ev_join, s_side);

    // ---- main stream: p1/p2 cvt + silu + bias, then gb GEMM + adaln ----
    prologue_main<<<4100, 256>>>(
        p1_w, p2_w, (const float4*)cond, (const float4*)p1_b, (const float4*)p2_b,
        wgb, (float4*)sc, (float4*)bgb);

    // gb12 = sc @ [p1_w|p2_w] + [p1_b|p2_b]   (4096x512 @ 512x4096, FUSED)
    tf32gemm<EPI_BIAS><<<dim3(32, 32), 256, GEMM_SMEM_BYTES>>>(
        sc, wgb, gb12, T_TOK, 4096, 512, 512, bgb, nullptr);

    // h = tf32(adaln(x, gamma1/beta1))
    adaln_kernel<<<T_TOK, 256>>>(x, gb12, 0, h);

    // ---- join: late weights must be ready before qkv GEMM ----
    cudaStreamWaitEvent(0, s_ev_join, 0);

    // qkv = h @ qkv_w  (4096x1024 @ 1024x3072)
    tf32gemm<EPI_NONE><<<dim3(24, 32), 256, GEMM_SMEM_BYTES>>>(
        h, wqkv, qkvp, T_TOK, 3072, 1024, 1024, nullptr, nullptr);

    // attention (HMMA tensor cores)
    attn_kernel<<<dim3(16, 32), 256, ATTN_SMEM_BYTES>>>(qkvp, attn);

    // x2 = x + attn @ attn_out_w  (4096x1024 @ 1024x1024)
    tf32gemm<EPI_RES><<<dim3(8, 32), 256, GEMM_SMEM_BYTES>>>(
        attn, wao, x2, T_TOK, 1024, 1024, 1024, nullptr, x);

    // h2 = tf32(adaln(x2, gamma2/beta2))
    adaln_kernel<<<T_TOK, 256>>>(x2, gb12, 2048, h2);

    // ff = tf32(gelu(h2 @ ffn_w1 + b1))  (4096x1024 @ 1024x4096)
    tf32gemm<EPI_BIAS_GELU><<<dim3(32, 32), 256, GEMM_SMEM_BYTES>>>(
        h2, wf1, ff, T_TOK, 4096, 1024, 1024, ffn_b1, nullptr);

    // f2 split-K x2: pk[z] = ff[:, z*2048:(z+1)*2048] @ wf2-chunk
    tf32gemm<EPI_NONE><<<dim3(8, 32, 2), 256, GEMM_SMEM_BYTES>>>(
        ff, wf2, pk, T_TOK, 1024, 4096, 2048, nullptr, nullptr);

    // out = pk0 + pk1 + b2 + x2
    reduce_bias_res<<<4096, 256>>>(
        (const float4*)pk, (const float4*)(pk + (size_t)T_TOK * 1024),
        (const float4*)ffn_b2, (const float4*)x2, (float4*)out);
}

// round 14
// speedup vs baseline: 1.0570x; 1.0554x over previous
#include <cuda_runtime.h>
#include <math.h>
#include <stdint.h>

// ---------------------------------------------------------------------------
// DecoderBlock (DiT-style): AdaLN -> MHA -> residual -> AdaLN -> FFN -> residual
// B=2, S=2048 (T=4096 tokens), D=1024, H=16, d=64, D_COND=512, FF=4096, fp32.
// tf32 HMMA. Weights pre-rounded tf32 + pre-transposed [N][K]; ldmatrix.x4;
// BK=16, 5-stage cp.async ring, 2 CTA/SM. Fused gb GEMM; split-K x2 for f2;
// side-stream weight cvt. Attention staging: vector STS, V row-major
// (conflict-free), K/V/P fed to HMMA as raw fp32 (HW tf32 truncation).
// ---------------------------------------------------------------------------

#define T_TOK 4096

__device__ float g_sc  [T_TOK * 512];
__device__ float g_gb12[T_TOK * 4096];   // fused [gamma1|beta1|gamma2|beta2]
__device__ float g_h   [T_TOK * 1024];
__device__ float g_qkv [T_TOK * 3072];
__device__ float g_attn[T_TOK * 1024];
__device__ float g_x2  [T_TOK * 1024];
__device__ float g_h2  [T_TOK * 1024];
__device__ float g_ff  [T_TOK * 4096];
__device__ float g_pk  [2 * T_TOK * 1024];   // f2 split-K partials
// tf32-rounded, TRANSPOSED ([N][K]) weight copies
__device__ float g_wgb [4096 * 512];
__device__ float g_bgb [4096];
__device__ float g_wqkv[3072 * 1024];
__device__ float g_wao [1024 * 1024];
__device__ float g_wf1 [4096 * 1024];
__device__ float g_wf2 [1024 * 4096];

enum { EPI_NONE = 0, EPI_BIAS = 1, EPI_BIAS_GELU = 2, EPI_RES = 3, EPI_BIAS_RES = 4 };

__device__ __forceinline__ float gelu_exact(float v) {
    return 0.5f * v * (1.0f + erff(v * 0.70710678118654752440f));
}

__device__ __forceinline__ float to_tf32(float x) {
    uint32_t u;
    asm("cvt.rna.tf32.f32 %0, %1;" : "=r"(u) : "f"(x));
    return __uint_as_float(u);
}

__device__ __forceinline__ void mma_tf32(float* c,
    uint32_t a0, uint32_t a1, uint32_t a2, uint32_t a3, uint32_t b0, uint32_t b1)
{
    asm volatile(
        "mma.sync.aligned.m16n8k8.row.col.f32.tf32.tf32.f32 "
        "{%0,%1,%2,%3},{%4,%5,%6,%7},{%8,%9},{%0,%1,%2,%3};\n"
        : "+f"(c[0]), "+f"(c[1]), "+f"(c[2]), "+f"(c[3])
        : "r"(a0), "r"(a1), "r"(a2), "r"(a3), "r"(b0), "r"(b1));
}

__device__ __forceinline__ void ldsm_x4(uint32_t* r, uint32_t saddr) {
    asm volatile("ldmatrix.sync.aligned.m8n8.x4.shared.b16 {%0,%1,%2,%3}, [%4];"
                 : "=r"(r[0]), "=r"(r[1]), "=r"(r[2]), "=r"(r[3]) : "r"(saddr));
}

__device__ __forceinline__ void cp16(float* smem_dst, const float* gsrc) {
    uint32_t d = (uint32_t)__cvta_generic_to_shared(smem_dst);
    asm volatile("cp.async.cg.shared.global [%0], [%1], 16;\n" :: "r"(d), "l"(gsrc));
}
__device__ __forceinline__ void cp_commit() {
    asm volatile("cp.async.commit_group;\n");
}
template <int N>
__device__ __forceinline__ void cp_wait() {
    asm volatile("cp.async.wait_group %0;\n" :: "n"(N));
}

// ---------------------------------------------------------------------------
// cvt+transpose tile body (32x32 via smem): dst[N][K] = tf32(src[K][N]^T)
// ---------------------------------------------------------------------------
__device__ __forceinline__ void cvt_tile(
    const float* __restrict__ src, float* __restrict__ dst,
    int K, int N, int tile, int tid)
{
    __shared__ float t[32][33];
    const int ntx = N >> 5;
    const int n0 = (tile % ntx) * 32;
    const int k0 = (tile / ntx) * 32;
    const int tx = tid & 31;
    const int ty = tid >> 5;
    #pragma unroll
    for (int i = 0; i < 32; i += 8)
        t[ty + i][tx] = to_tf32(src[(size_t)(k0 + ty + i) * N + n0 + tx]);
    __syncthreads();
    #pragma unroll
    for (int i = 0; i < 32; i += 8)
        dst[(size_t)(n0 + ty + i) * K + k0 + tx] = t[tx][ty + i];
}

// Main-stream prologue: p1/p2 cvt (2048 tiles) + silu (2048) + bias (4)
__global__ __launch_bounds__(256) void prologue_main(
    const float* __restrict__ p1, const float* __restrict__ p2,
    const float4* __restrict__ cond,
    const float4* __restrict__ b1, const float4* __restrict__ b2,
    float* __restrict__ ogb, float4* __restrict__ sc, float4* __restrict__ bgb)
{
    int blk = blockIdx.x;
    int tid = threadIdx.x;
    if (blk < 1024) {
        cvt_tile(p1, ogb, 512, 2048, blk, tid);
    } else if (blk < 2048) {
        cvt_tile(p2, ogb + 2048 * 512, 512, 2048, blk - 1024, tid);
    } else if (blk < 4096) {
        int i = (blk - 2048) * 256 + tid;
        float4 v = cond[i];
        sc[i] = make_float4(
            to_tf32(v.x / (1.0f + __expf(-v.x))),
            to_tf32(v.y / (1.0f + __expf(-v.y))),
            to_tf32(v.z / (1.0f + __expf(-v.z))),
            to_tf32(v.w / (1.0f + __expf(-v.w))));
    } else {
        int i = (blk - 4096) * 256 + tid;
        bgb[i] = (i < 512) ? b1[i] : b2[i - 512];
    }
}

// Side-stream prologue: qkv/ao/f1/f2 cvt (12288 tiles)
__global__ __launch_bounds__(256) void prologue_side(
    const float* __restrict__ qk, const float* __restrict__ ao,
    const float* __restrict__ f1, const float* __restrict__ f2,
    float* __restrict__ oq, float* __restrict__ oa,
    float* __restrict__ of1, float* __restrict__ of2)
{
    int blk = blockIdx.x;
    int tid = threadIdx.x;
    if      (blk < 3072)  cvt_tile(qk, oq,  1024, 3072, blk, tid);
    else if (blk < 4096)  cvt_tile(ao, oa,  1024, 1024, blk - 3072, tid);
    else if (blk < 8192)  cvt_tile(f1, of1, 1024, 4096, blk - 4096, tid);
    else                  cvt_tile(f2, of2, 4096, 1024, blk - 8192, tid);
}

// ---------------------------------------------------------------------------
// tf32 GEMM: C(MxN) = A(MxK) @ Bt(NxK)^T [+bias][+gelu][+res]
// Block 128x128, BK=16, 256 threads, warp tile 64x32, 5-stage cp.async,
// ldmatrix.x4 frags, 2 CTAs/SM. Split-K via blockIdx.z.
// ---------------------------------------------------------------------------
#define GST (128 * 20)
#define GSS (2 * GST)
#define GEMM_STAGES 5
#define GEMM_SMEM_BYTES (GEMM_STAGES * GSS * 4)

template <int EPI>
__global__ __launch_bounds__(256, 2) void tf32gemm(
    const float* __restrict__ A, const float* __restrict__ Bt, float* __restrict__ C,
    int M, int N, int Kstride, int Klen,
    const float* __restrict__ bias, const float* __restrict__ res)
{
    extern __shared__ float sm[];

    const int tid  = threadIdx.x;
    const int bx   = blockIdx.x;
    const int by   = blockIdx.y;
    const int kz   = blockIdx.z;
    const int lane = tid & 31;
    const int wid  = tid >> 5;
    const int wm   = (wid >> 2) * 64;
    const int wn   = (wid & 3) * 32;
    const int gr   = lane >> 2;
    const int gc   = lane & 3;

    const int rowsel = (lane & 7) + ((lane >> 3) & 1) * 8;
    const int kadd   = (lane >> 4) * 4;

    const int srow = tid >> 1;
    const int scol = (tid & 1) * 8;
    const size_t koff = (size_t)kz * Klen;
    const float* Agb = A  + (size_t)(by * 128 + srow) * Kstride + koff + scol;
    const float* Bgb = Bt + (size_t)(bx * 128 + srow) * Kstride + koff + scol;
    C += (size_t)kz * M * N;

    const int nk = Klen >> 4;

    float acc[4][4][4];
    #pragma unroll
    for (int mi = 0; mi < 4; mi++)
        #pragma unroll
        for (int ni = 0; ni < 4; ni++)
            #pragma unroll
            for (int q = 0; q < 4; q++) acc[mi][ni][q] = 0.0f;

    #pragma unroll
    for (int s = 0; s < GEMM_STAGES - 1; s++) {
        float* as = sm + s * GSS;
        float* bs = as + GST;
        cp16(as + srow * 20 + scol,     Agb + s * 16);
        cp16(as + srow * 20 + scol + 4, Agb + s * 16 + 4);
        cp16(bs + srow * 20 + scol,     Bgb + s * 16);
        cp16(bs + srow * 20 + scol + 4, Bgb + s * 16 + 4);
        cp_commit();
    }

    const uint32_t smemBase = (uint32_t)__cvta_generic_to_shared(sm);

    for (int kt = 0; kt < nk; kt++) {
        cp_wait<GEMM_STAGES - 2>();
        __syncthreads();

        if (kt + GEMM_STAGES - 1 < nk) {
            int s = (kt + GEMM_STAGES - 1) % GEMM_STAGES;
            float* as = sm + s * GSS;
            float* bs = as + GST;
            cp16(as + srow * 20 + scol,     Agb + (kt + GEMM_STAGES - 1) * 16);
            cp16(as + srow * 20 + scol + 4, Agb + (kt + GEMM_STAGES - 1) * 16 + 4);
            cp16(bs + srow * 20 + scol,     Bgb + (size_t)(kt + GEMM_STAGES - 1) * 16);
            cp16(bs + srow * 20 + scol + 4, Bgb + (size_t)(kt + GEMM_STAGES - 1) * 16 + 4);
        }
        cp_commit();

        const uint32_t asAddr = smemBase + ((kt % GEMM_STAGES) * GSS) * 4;
        const uint32_t bsAddr = asAddr + GST * 4;
        const uint32_t aBase = asAddr + ((wm + rowsel) * 20 + kadd) * 4;
        const uint32_t bBase = bsAddr + ((wn + rowsel) * 20 + kadd) * 4;

        #pragma unroll
        for (int k8 = 0; k8 < 16; k8 += 8) {
            uint32_t af[4][4], bf[2][4];
            #pragma unroll
            for (int mi = 0; mi < 4; mi++)
                ldsm_x4(af[mi], aBase + (mi * 16 * 20 + k8) * 4);
            #pragma unroll
            for (int p = 0; p < 2; p++)
                ldsm_x4(bf[p], bBase + (p * 16 * 20 + k8) * 4);
            #pragma unroll
            for (int mi = 0; mi < 4; mi++)
                #pragma unroll
                for (int ni = 0; ni < 4; ni++)
                    mma_tf32(acc[mi][ni], af[mi][0], af[mi][1], af[mi][2], af[mi][3],
                             bf[ni >> 1][ni & 1], bf[ni >> 1][2 + (ni & 1)]);
        }
        __syncthreads();
    }

    #pragma unroll
    for (int mi = 0; mi < 4; mi++) {
        #pragma unroll
        for (int half = 0; half < 2; half++) {
            int r = by * 128 + wm + mi * 16 + gr + half * 8;
            size_t rowbase = (size_t)r * N + (size_t)bx * 128;
            #pragma unroll
            for (int ni = 0; ni < 4; ni++) {
                int c = wn + ni * 8 + gc * 2;
                float v0 = acc[mi][ni][half * 2 + 0];
                float v1 = acc[mi][ni][half * 2 + 1];
                if (EPI == EPI_BIAS || EPI == EPI_BIAS_GELU || EPI == EPI_BIAS_RES) {
                    v0 += bias[bx * 128 + c];
                    v1 += bias[bx * 128 + c + 1];
                }
                if (EPI == EPI_BIAS_GELU) {
                    v0 = to_tf32(gelu_exact(v0));
                    v1 = to_tf32(gelu_exact(v1));
                }
                if (EPI == EPI_RES || EPI == EPI_BIAS_RES) {
                    v0 += res[rowbase + c];
                    v1 += res[rowbase + c + 1];
                }
                *reinterpret_cast<float2*>(&C[rowbase + c]) = make_float2(v0, v1);
            }
        }
    }
}

// ---------------------------------------------------------------------------
// Split-K reduce: out = p0 + p1 + bias + res
// ---------------------------------------------------------------------------
__global__ void reduce_bias_res(
    const float4* __restrict__ p0, const float4* __restrict__ p1,
    const float4* __restrict__ bias, const float4* __restrict__ res,
    float4* __restrict__ out)
{
    int i = blockIdx.x * blockDim.x + threadIdx.x;
    float4 a = p0[i], b = p1[i], c = bias[i & 255], d = res[i];
    out[i] = make_float4(a.x + b.x + c.x + d.x,
                         a.y + b.y + c.y + d.y,
                         a.z + b.z + c.z + d.z,
                         a.w + b.w + c.w + d.w);
}

// ---------------------------------------------------------------------------
// Block reduce (256 threads = 8 warps)
// ---------------------------------------------------------------------------
__device__ __forceinline__ float blockReduceSum256(float v)
{
    __shared__ float sh[8];
    int lane = threadIdx.x & 31;
    int wid  = threadIdx.x >> 5;
    #pragma unroll
    for (int o = 16; o; o >>= 1) v += __shfl_xor_sync(0xffffffffu, v, o);
    __syncthreads();
    if (lane == 0) sh[wid] = v;
    __syncthreads();
    float s = 0.0f;
    #pragma unroll
    for (int i = 0; i < 8; i++) s += sh[i];
    return s;
}

// ---------------------------------------------------------------------------
// AdaLN (output tf32-rounded). gb row layout [g1|b1|g2|b2], stride 4096.
// ---------------------------------------------------------------------------
__global__ __launch_bounds__(256) void adaln_kernel(
    const float* __restrict__ x, const float* __restrict__ gb, int off,
    float* __restrict__ h)
{
    int row = blockIdx.x;
    int t   = threadIdx.x;
    const float* xr = x + (size_t)row * 1024;

    float4 v = *reinterpret_cast<const float4*>(xr + t * 4);
    float s = v.x + v.y + v.z + v.w;
    s = blockReduceSum256(s);
    float mu = s * (1.0f / 1024.0f);

    float dx = v.x - mu, dy = v.y - mu, dz = v.z - mu, dw = v.w - mu;
    float s2 = dx * dx + dy * dy + dz * dz + dw * dw;
    s2 = blockReduceSum256(s2);
    float rstd = rsqrtf(s2 * (1.0f / 1024.0f) + 1e-5f);

    const float* gbr = gb + (size_t)row * 4096 + off;
    float4 g = *reinterpret_cast<const float4*>(gbr + t * 4);
    float4 b = *reinterpret_cast<const float4*>(gbr + 1024 + t * 4);

    float4 o;
    o.x = to_tf32(dx * rstd * (1.0f + g.x) + b.x);
    o.y = to_tf32(dy * rstd * (1.0f + g.y) + b.y);
    o.z = to_tf32(dz * rstd * (1.0f + g.z) + b.z);
    o.w = to_tf32(dw * rstd * (1.0f + g.w) + b.w);
    *reinterpret_cast<float4*>(h + (size_t)row * 1024 + t * 4) = o;
}

// ---------------------------------------------------------------------------
// Tensor-core flash attention (tf32 HMMA). Q-tile 128, KV-tile 64, 8 warps.
// Lean staging: K and V staged with vector STS (V row-major, pad 72 ->
// conflict-free B-frag loads); K/V/P fed raw fp32 (HW tf32 truncation).
// smem: Qs 128x68 | Ks 64x68 | Vs 64x72 | Ps 128x68 = 105472 B (2 CTA/SM).
// ---------------------------------------------------------------------------
#define QS_STRIDE 68
#define VS_STRIDE 72
#define ATTN_SMEM_FLOATS (128 * 68 + 64 * 68 + 64 * 72 + 128 * 68)
#define ATTN_SMEM_BYTES  (ATTN_SMEM_FLOATS * 4)

__global__ __launch_bounds__(256) void attn_kernel(
    const float* __restrict__ qkv, float* __restrict__ out)
{
    extern __shared__ float sm[];
    float (*Qs)[QS_STRIDE] = (float(*)[QS_STRIDE])(sm);
    float (*Ks)[QS_STRIDE] = (float(*)[QS_STRIDE])(sm + 128 * 68);
    float (*Vs)[VS_STRIDE] = (float(*)[VS_STRIDE])(sm + 128 * 68 + 64 * 68);
    float (*Ps)[QS_STRIDE] = (float(*)[QS_STRIDE])(sm + 128 * 68 + 64 * 68 + 64 * 72);

    const int qt  = blockIdx.x;
    const int bh  = blockIdx.y;
    const int b   = bh >> 4;
    const int hd  = bh & 15;
    const int tok0 = b * 2048;
    const int qb = hd * 64, kb = 1024 + hd * 64, vb = 2048 + hd * 64;

    const int tid  = threadIdx.x;
    const int lane = tid & 31;
    const int wid  = tid >> 5;
    const int wm   = wid * 16;
    const int gr   = lane >> 2;
    const int gc   = lane & 3;

    const int lr = tid >> 4;
    const int lc = (tid & 15) * 4;

    // Q: scaled + tf32-rounded once (off the per-iter path)
    #pragma unroll
    for (int s = 0; s < 8; s++) {
        int r = lr + s * 16;
        float4 v = *reinterpret_cast<const float4*>(
            &qkv[(size_t)(tok0 + qt * 128 + r) * 3072 + qb + lc]);
        Qs[r][lc + 0] = to_tf32(0.125f * v.x);
        Qs[r][lc + 1] = to_tf32(0.125f * v.y);
        Qs[r][lc + 2] = to_tf32(0.125f * v.z);
        Qs[r][lc + 3] = to_tf32(0.125f * v.w);
    }

    float4 kr4[4], vr4[4];
    #pragma unroll
    for (int s = 0; s < 4; s++) {
        size_t base = (size_t)(tok0 + lr + s * 16) * 3072;
        kr4[s] = *reinterpret_cast<const float4*>(&qkv[base + kb + lc]);
        vr4[s] = *reinterpret_cast<const float4*>(&qkv[base + vb + lc]);
    }

    float m0 = -1e30f, m1 = -1e30f, l0 = 0.0f, l1 = 0.0f;
    float o[8][4];
    #pragma unroll
    for (int nt = 0; nt < 8; nt++)
        #pragma unroll
        for (int q = 0; q < 4; q++) o[nt][q] = 0.0f;

    for (int kt = 0; kt < 32; kt++) {
        // lean staging: vector STS, no transpose, no cvt
        #pragma unroll
        for (int s = 0; s < 4; s++) {
            int r = lr + s * 16;
            *reinterpret_cast<float4*>(&Ks[r][lc]) = kr4[s];
            *reinterpret_cast<float4*>(&Vs[r][lc]) = vr4[s];
        }
        __syncthreads();

        if (kt + 1 < 32) {
            #pragma unroll
            for (int s = 0; s < 4; s++) {
                size_t base = (size_t)(tok0 + (kt + 1) * 64 + lr + s * 16) * 3072;
                kr4[s] = *reinterpret_cast<const float4*>(&qkv[base + kb + lc]);
                vr4[s] = *reinterpret_cast<const float4*>(&qkv[base + vb + lc]);
            }
        }

        float sacc[8][4];
        #pragma unroll
        for (int nt = 0; nt < 8; nt++)
            #pragma unroll
            for (int q = 0; q < 4; q++) sacc[nt][q] = 0.0f;

        #pragma unroll
        for (int k8 = 0; k8 < 64; k8 += 8) {
            uint32_t a0 = __float_as_uint(Qs[wm + gr    ][k8 + gc]);
            uint32_t a1 = __float_as_uint(Qs[wm + gr + 8][k8 + gc]);
            uint32_t a2 = __float_as_uint(Qs[wm + gr    ][k8 + gc + 4]);
            uint32_t a3 = __float_as_uint(Qs[wm + gr + 8][k8 + gc + 4]);
            #pragma unroll
            for (int nt = 0; nt < 8; nt++) {
                uint32_t b0 = __float_as_uint(Ks[nt * 8 + gr][k8 + gc]);
                uint32_t b1 = __float_as_uint(Ks[nt * 8 + gr][k8 + gc + 4]);
                mma_tf32(sacc[nt], a0, a1, a2, a3, b0, b1);
            }
        }

        float rm0 = -1e30f, rm1 = -1e30f;
        #pragma unroll
        for (int nt = 0; nt < 8; nt++) {
            rm0 = fmaxf(rm0, fmaxf(sacc[nt][0], sacc[nt][1]));
            rm1 = fmaxf(rm1, fmaxf(sacc[nt][2], sacc[nt][3]));
        }
        rm0 = fmaxf(rm0, __shfl_xor_sync(0xffffffffu, rm0, 1));
        rm0 = fmaxf(rm0, __shfl_xor_sync(0xffffffffu, rm0, 2));
        rm1 = fmaxf(rm1, __shfl_xor_sync(0xffffffffu, rm1, 1));
        rm1 = fmaxf(rm1, __shfl_xor_sync(0xffffffffu, rm1, 2));

        float mn0 = fmaxf(m0, rm0);
        float mn1 = fmaxf(m1, rm1);
        float al0 = __expf(m0 - mn0);
        float al1 = __expf(m1 - mn1);
        m0 = mn0; m1 = mn1;

        float sum0 = 0.0f, sum1 = 0.0f;
        #pragma unroll
        for (int nt = 0; nt < 8; nt++) {
            float p0 = __expf(sacc[nt][0] - mn0);
            float p1 = __expf(sacc[nt][1] - mn0);
            float p2 = __expf(sacc[nt][2] - mn1);
            float p3 = __expf(sacc[nt][3] - mn1);
            sum0 += p0 + p1;
            sum1 += p2 + p3;
            *reinterpret_cast<float2*>(&Ps[wm + gr    ][nt * 8 + 2 * gc]) =
                make_float2(p0, p1);
            *reinterpret_cast<float2*>(&Ps[wm + gr + 8][nt * 8 + 2 * gc]) =
                make_float2(p2, p3);
        }
        sum0 += __shfl_xor_sync(0xffffffffu, sum0, 1);
        sum0 += __shfl_xor_sync(0xffffffffu, sum0, 2);
        sum1 += __shfl_xor_sync(0xffffffffu, sum1, 1);
        sum1 += __shfl_xor_sync(0xffffffffu, sum1, 2);
        l0 = l0 * al0 + sum0;
        l1 = l1 * al1 + sum1;

        #pragma unroll
        for (int nt = 0; nt < 8; nt++) {
            o[nt][0] *= al0; o[nt][1] *= al0;
            o[nt][2] *= al1; o[nt][3] *= al1;
        }
        __syncwarp();

        // O += P @ V   (B-frag from row-major Vs; pad 72 -> conflict-free)
        #pragma unroll
        for (int k8 = 0; k8 < 64; k8 += 8) {
            uint32_t a0 = __float_as_uint(Ps[wm + gr    ][k8 + gc]);
            uint32_t a1 = __float_as_uint(Ps[wm + gr + 8][k8 + gc]);
            uint32_t a2 = __float_as_uint(Ps[wm + gr    ][k8 + gc + 4]);
            uint32_t a3 = __float_as_uint(Ps[wm + gr + 8][k8 + gc + 4]);
            #pragma unroll
            for (int nt = 0; nt < 8; nt++) {
                uint32_t b0 = __float_as_uint(Vs[k8 + gc    ][nt * 8 + gr]);
                uint32_t b1 = __float_as_uint(Vs[k8 + gc + 4][nt * 8 + gr]);
                mma_tf32(o[nt], a0, a1, a2, a3, b0, b1);
            }
        }
        __syncthreads();
    }

    float inv0 = 1.0f / l0;
    float inv1 = 1.0f / l1;
    int t0 = tok0 + qt * 128 + wm + gr;
    int t1 = t0 + 8;
    #pragma unroll
    for (int nt = 0; nt < 8; nt++) {
        int col = hd * 64 + nt * 8 + 2 * gc;
        *reinterpret_cast<float2*>(&out[(size_t)t0 * 1024 + col]) =
            make_float2(to_tf32(o[nt][0] * inv0), to_tf32(o[nt][1] * inv0));
        *reinterpret_cast<float2*>(&out[(size_t)t1 * 1024 + col]) =
            make_float2(to_tf32(o[nt][2] * inv1), to_tf32(o[nt][3] * inv1));
    }
}

// ---------------------------------------------------------------------------
// Launch
// ---------------------------------------------------------------------------
extern "C" void kernel_launch(void* const* d_in, const int* in_sizes, int n_in,
                              void* d_out, int out_size)
{
    const float* x        = (const float*)d_in[0];
    const float* cond     = (const float*)d_in[1];
    const float* p1_w     = (const float*)d_in[2];
    const float* p1_b     = (const float*)d_in[3];
    const float* qkv_w    = (const float*)d_in[4];
    const float* attn_o_w = (const float*)d_in[5];
    const float* p2_w     = (const float*)d_in[6];
    const float* p2_b     = (const float*)d_in[7];
    const float* ffn_w1   = (const float*)d_in[8];
    const float* ffn_b1   = (const float*)d_in[9];
    const float* ffn_w2   = (const float*)d_in[10];
    const float* ffn_b2   = (const float*)d_in[11];
    float* out = (float*)d_out;

    float *sc, *gb12, *h, *qkvp, *attn, *x2, *h2, *ff, *pk;
    float *wgb, *bgb, *wqkv, *wao, *wf1, *wf2;
    cudaGetSymbolAddress((void**)&sc,   g_sc);
    cudaGetSymbolAddress((void**)&gb12, g_gb12);
    cudaGetSymbolAddress((void**)&h,    g_h);
    cudaGetSymbolAddress((void**)&qkvp, g_qkv);
    cudaGetSymbolAddress((void**)&attn, g_attn);
    cudaGetSymbolAddress((void**)&x2,   g_x2);
    cudaGetSymbolAddress((void**)&h2,   g_h2);
    cudaGetSymbolAddress((void**)&ff,   g_ff);
    cudaGetSymbolAddress((void**)&pk,   g_pk);
    cudaGetSymbolAddress((void**)&wgb,  g_wgb);
    cudaGetSymbolAddress((void**)&bgb,  g_bgb);
    cudaGetSymbolAddress((void**)&wqkv, g_wqkv);
    cudaGetSymbolAddress((void**)&wao,  g_wao);
    cudaGetSymbolAddress((void**)&wf1,  g_wf1);
    cudaGetSymbolAddress((void**)&wf2,  g_wf2);

    static cudaStream_t s_side = nullptr;
    static cudaEvent_t  s_ev_fork = nullptr, s_ev_join = nullptr;
    static int attr_done = 0;
    if (!attr_done) {
        cudaFuncSetAttribute(attn_kernel, cudaFuncAttributeMaxDynamicSharedMemorySize, ATTN_SMEM_BYTES);
        cudaFuncSetAttribute(tf32gemm<EPI_NONE>,      cudaFuncAttributeMaxDynamicSharedMemorySize, GEMM_SMEM_BYTES);
        cudaFuncSetAttribute(tf32gemm<EPI_BIAS>,      cudaFuncAttributeMaxDynamicSharedMemorySize, GEMM_SMEM_BYTES);
        cudaFuncSetAttribute(tf32gemm<EPI_BIAS_GELU>, cudaFuncAttributeMaxDynamicSharedMemorySize, GEMM_SMEM_BYTES);
        cudaFuncSetAttribute(tf32gemm<EPI_RES>,       cudaFuncAttributeMaxDynamicSharedMemorySize, GEMM_SMEM_BYTES);
        cudaFuncSetAttribute(tf32gemm<EPI_BIAS_RES>,  cudaFuncAttributeMaxDynamicSharedMemorySize, GEMM_SMEM_BYTES);
        cudaStreamCreateWithFlags(&s_side, cudaStreamNonBlocking);
        cudaEventCreateWithFlags(&s_ev_fork, cudaEventDisableTiming);
        cudaEventCreateWithFlags(&s_ev_join, cudaEventDisableTiming);
        attr_done = 1;
    }

    // ---- fork: side stream converts the 4 late weights ----
    cudaEventRecord(s_ev_fork, 0);
    cudaStreamWaitEvent(s_side, s_ev_fork, 0);
    prologue_side<<<12288, 256, 0, s_side>>>(
        qkv_w, attn_o_w, ffn_w1, ffn_w2, wqkv, wao, wf1, wf2);
    cudaEventRecord(s_ev_join, s_side);

    // ---- main stream ----
    prologue_main<<<4100, 256>>>(
        p1_w, p2_w, (const float4*)cond, (const float4*)p1_b, (const float4*)p2_b,
        wgb, (float4*)sc, (float4*)bgb);

    // gb12 = sc @ [p1_w|p2_w] + [p1_b|p2_b]
    tf32gemm<EPI_BIAS><<<dim3(32, 32), 256, GEMM_SMEM_BYTES>>>(
        sc, wgb, gb12, T_TOK, 4096, 512, 512, bgb, nullptr);

    // h = tf32(adaln(x, gamma1/beta1))
    adaln_kernel<<<T_TOK, 256>>>(x, gb12, 0, h);

    cudaStreamWaitEvent(0, s_ev_join, 0);

    // qkv = h @ qkv_w
    tf32gemm<EPI_NONE><<<dim3(24, 32), 256, GEMM_SMEM_BYTES>>>(
        h, wqkv, qkvp, T_TOK, 3072, 1024, 1024, nullptr, nullptr);

    // attention
    attn_kernel<<<dim3(16, 32), 256, ATTN_SMEM_BYTES>>>(qkvp, attn);

    // x2 = x + attn @ attn_out_w
    tf32gemm<EPI_RES><<<dim3(8, 32), 256, GEMM_SMEM_BYTES>>>(
        attn, wao, x2, T_TOK, 1024, 1024, 1024, nullptr, x);

    // h2 = tf32(adaln(x2, gamma2/beta2))
    adaln_kernel<<<T_TOK, 256>>>(x2, gb12, 2048, h2);

    // ff = tf32(gelu(h2 @ ffn_w1 + b1))
    tf32gemm<EPI_BIAS_GELU><<<dim3(32, 32), 256, GEMM_SMEM_BYTES>>>(
        h2, wf1, ff, T_TOK, 4096, 1024, 1024, ffn_b1, nullptr);

    // f2 split-K x2
    tf32gemm<EPI_NONE><<<dim3(8, 32, 2), 256, GEMM_SMEM_BYTES>>>(
        ff, wf2, pk, T_TOK, 1024, 4096, 2048, nullptr, nullptr);

    // out = pk0 + pk1 + b2 + x2
    reduce_bias_res<<<4096, 256>>>(
        (const float4*)pk, (const float4*)(pk + (size_t)T_TOK * 1024),
        (const float4*)ffn_b2, (const float4*)x2, (float4*)out);
}